// round 1
// baseline (speedup 1.0000x reference)
#include <cuda_runtime.h>
#include <cstddef>

#define DD 128
#define VMAX 100000

// Scratch: Y_in (V rows) followed by Y_out (V rows), each [V,128] f32.
__device__ float g_Y[2u * VMAX * DD];          // 102.4 MB, zeroed per launch
__device__ float g_stats[2 * DD];              // [0:128]=sum, [128:256]=sumsq

// ---------------------------------------------------------------------------
// Kernel 1: per-edge scatter.  Y_dir[dst] += norm * (x[src] * rel[et])
// One warp per edge, each lane owns 4 channels (float4).
// ---------------------------------------------------------------------------
__global__ void edge_kernel(const float* __restrict__ x,
                            const float* __restrict__ rel,
                            const float* __restrict__ enorm,
                            const int* __restrict__ src,
                            const int* __restrict__ dst,
                            const int* __restrict__ et,
                            int E, int V, int half) {
    int warp = (blockIdx.x * blockDim.x + threadIdx.x) >> 5;
    if (warp >= E) return;
    int lane = threadIdx.x & 31;

    int   s = __ldg(&src[warp]);
    int   d = __ldg(&dst[warp]);
    int   t = __ldg(&et[warp]);
    float n = __ldg(&enorm[warp]);

    float4 xv = __ldg(reinterpret_cast<const float4*>(x)   + (size_t)s * 32 + lane);
    float4 rv = __ldg(reinterpret_cast<const float4*>(rel) + (size_t)t * 32 + lane);

    float a = n * xv.x * rv.x;
    float b = n * xv.y * rv.y;
    float c = n * xv.z * rv.z;
    float w = n * xv.w * rv.w;

    float* yp = g_Y + (size_t)((warp < half ? 0 : V) + d) * DD + lane * 4;
    asm volatile("red.global.add.v4.f32 [%0], {%1,%2,%3,%4};"
                 :: "l"(yp), "f"(a), "f"(b), "f"(c), "f"(w) : "memory");
}

// ---------------------------------------------------------------------------
// Kernel 2: fused GEMM over stacked K=384:
//   h[v] = ( Yin[v]@in_w + Yout[v]@out_w + (x[v]*loop_rel)@loop_w ) / 3 + bias
// Tile: 64 nodes x 128 cols per block, 256 threads, 8x4 register tile.
// Also accumulates per-column sum / sumsq into g_stats for BatchNorm.
// ---------------------------------------------------------------------------
__global__ void __launch_bounds__(256) gemm_kernel(
    const float* __restrict__ x,
    const float* __restrict__ loop_rel,
    const float* __restrict__ in_w,
    const float* __restrict__ out_w,
    const float* __restrict__ loop_w,
    const float* __restrict__ bias,
    float* __restrict__ hout,
    int V) {

    __shared__ float Ws[16][128];   // W chunk  [k][col]
    __shared__ float Zs[16][64];    // Z chunk  [k][node] (transposed)
    __shared__ float ssum[128];
    __shared__ float ssq[128];

    const int tid = threadIdx.x;
    const int tx  = tid & 31;   // col group: cols tx*4 .. tx*4+3
    const int ty  = tid >> 5;   // node group: nodes ty*8 .. ty*8+7
    const int m0  = blockIdx.x * 64;

    float acc[8][4];
#pragma unroll
    for (int r = 0; r < 8; r++)
#pragma unroll
        for (int c = 0; c < 4; c++) acc[r][c] = 0.f;

    const int zr = tid & 63;    // node within tile for Z loads
    const int zk = tid >> 6;    // 0..3 -> k sub-offset

    for (int kc = 0; kc < 384; kc += 16) {
        // --- load W chunk (16 x 128) ---
        const float* Wsrc = (kc < 128) ? in_w : (kc < 256 ? out_w : loop_w);
        const int kb = kc & 127;
#pragma unroll
        for (int i = 0; i < 2; i++) {
            int idx = tid + i * 256;            // 0..511 float4 slots
            int kk  = idx >> 5;                 // 0..15
            int cc  = (idx & 31) << 2;          // 0..124
            float4 w4 = __ldg(reinterpret_cast<const float4*>(Wsrc + (size_t)(kb + kk) * 128 + cc));
            *reinterpret_cast<float4*>(&Ws[kk][cc]) = w4;
        }
        // --- load Z chunk (64 nodes x 16 k), transposed into smem ---
        {
            int v = m0 + zr;
            float4 z = make_float4(0.f, 0.f, 0.f, 0.f);
            if (v < V) {
                if (kc < 256) {
                    const float* base = g_Y + (size_t)(kc < 128 ? v : V + v) * DD + (kc & 127) + zk * 4;
                    z = *reinterpret_cast<const float4*>(base);
                } else {
                    int ko = (kc - 256) + zk * 4;
                    float4 xv = __ldg(reinterpret_cast<const float4*>(x + (size_t)v * DD + ko));
                    float4 lr = __ldg(reinterpret_cast<const float4*>(loop_rel + ko));
                    z = make_float4(xv.x * lr.x, xv.y * lr.y, xv.z * lr.z, xv.w * lr.w);
                }
            }
            Zs[zk * 4 + 0][zr] = z.x;
            Zs[zk * 4 + 1][zr] = z.y;
            Zs[zk * 4 + 2][zr] = z.z;
            Zs[zk * 4 + 3][zr] = z.w;
        }
        __syncthreads();

#pragma unroll
        for (int k = 0; k < 16; k++) {
            float4 w4 = *reinterpret_cast<const float4*>(&Ws[k][tx * 4]);
            float4 za = *reinterpret_cast<const float4*>(&Zs[k][ty * 8]);
            float4 zb = *reinterpret_cast<const float4*>(&Zs[k][ty * 8 + 4]);
            float zz[8] = {za.x, za.y, za.z, za.w, zb.x, zb.y, zb.z, zb.w};
#pragma unroll
            for (int r = 0; r < 8; r++) {
                acc[r][0] += zz[r] * w4.x;
                acc[r][1] += zz[r] * w4.y;
                acc[r][2] += zz[r] * w4.z;
                acc[r][3] += zz[r] * w4.w;
            }
        }
        __syncthreads();
    }

    // --- epilogue: scale, bias, store h, accumulate BN stats ---
    if (tid < 128) { ssum[tid] = 0.f; ssq[tid] = 0.f; }
    __syncthreads();

    float4 bv = __ldg(reinterpret_cast<const float4*>(bias + tx * 4));
    const float third = 1.f / 3.f;
    float cs[4] = {0.f, 0.f, 0.f, 0.f};
    float cq[4] = {0.f, 0.f, 0.f, 0.f};

#pragma unroll
    for (int r = 0; r < 8; r++) {
        int v = m0 + ty * 8 + r;
        if (v < V) {
            float h0 = acc[r][0] * third + bv.x;
            float h1 = acc[r][1] * third + bv.y;
            float h2 = acc[r][2] * third + bv.z;
            float h3 = acc[r][3] * third + bv.w;
            float4 h4 = make_float4(h0, h1, h2, h3);
            *reinterpret_cast<float4*>(hout + (size_t)v * DD + tx * 4) = h4;
            cs[0] += h0; cq[0] += h0 * h0;
            cs[1] += h1; cq[1] += h1 * h1;
            cs[2] += h2; cq[2] += h2 * h2;
            cs[3] += h3; cq[3] += h3 * h3;
        }
    }
#pragma unroll
    for (int c = 0; c < 4; c++) {
        atomicAdd(&ssum[tx * 4 + c], cs[c]);
        atomicAdd(&ssq [tx * 4 + c], cq[c]);
    }
    __syncthreads();
    if (tid < 128) {
        atomicAdd(&g_stats[tid],       ssum[tid]);
        atomicAdd(&g_stats[128 + tid], ssq[tid]);
    }
}

// ---------------------------------------------------------------------------
// Kernel 3: BatchNorm (batch stats, gamma=1, beta=0) + ReLU, in place on h.
// ---------------------------------------------------------------------------
__global__ void bn_kernel(float* __restrict__ h, int V) {
    __shared__ float ms[128];
    __shared__ float rs[128];
    if (threadIdx.x < 128) {
        float invn = 1.f / (float)V;
        float s  = g_stats[threadIdx.x];
        float sq = g_stats[128 + threadIdx.x];
        float m  = s * invn;
        float var = sq * invn - m * m;
        ms[threadIdx.x] = m;
        rs[threadIdx.x] = rsqrtf(var + 1e-5f);
    }
    __syncthreads();

    size_t total = (size_t)V * 32;  // number of float4
    float4* h4 = reinterpret_cast<float4*>(h);
    for (size_t i = (size_t)blockIdx.x * blockDim.x + threadIdx.x; i < total;
         i += (size_t)gridDim.x * blockDim.x) {
        int c4 = (int)(i & 31) * 4;
        float4 hv = h4[i];
        hv.x = fmaxf((hv.x - ms[c4 + 0]) * rs[c4 + 0], 0.f);
        hv.y = fmaxf((hv.y - ms[c4 + 1]) * rs[c4 + 1], 0.f);
        hv.z = fmaxf((hv.z - ms[c4 + 2]) * rs[c4 + 2], 0.f);
        hv.w = fmaxf((hv.w - ms[c4 + 3]) * rs[c4 + 3], 0.f);
        h4[i] = hv;
    }
}

// ---------------------------------------------------------------------------
// Kernel 4: second output  rel_repr @ w_rel   [474,128]@[128,128]
// ---------------------------------------------------------------------------
__global__ void relw_kernel(const float* __restrict__ rel,
                            const float* __restrict__ w_rel,
                            float* __restrict__ out) {
    __shared__ float rrow[128];
    int r = blockIdx.x;
    int c = threadIdx.x;
    rrow[c] = rel[(size_t)r * 128 + c];
    __syncthreads();
    float acc = 0.f;
#pragma unroll 8
    for (int k = 0; k < 128; k++)
        acc += rrow[k] * __ldg(&w_rel[(size_t)k * 128 + c]);
    out[(size_t)r * 128 + c] = acc;
}

// ---------------------------------------------------------------------------
extern "C" void kernel_launch(void* const* d_in, const int* in_sizes, int n_in,
                              void* d_out, int out_size) {
    const float* x        = (const float*)d_in[0];
    const float* rel      = (const float*)d_in[1];
    const float* enorm    = (const float*)d_in[2];
    const float* in_w     = (const float*)d_in[3];
    const float* out_w    = (const float*)d_in[4];
    const float* loop_w   = (const float*)d_in[5];
    const float* w_rel    = (const float*)d_in[6];
    const float* loop_rel = (const float*)d_in[7];
    const float* bias     = (const float*)d_in[8];
    const int*   src      = (const int*)d_in[9];
    const int*   dst      = (const int*)d_in[10];
    const int*   et       = (const int*)d_in[11];

    int V = in_sizes[0] / DD;
    int R = in_sizes[1] / DD;
    int E = in_sizes[2];

    float* h    = (float*)d_out;
    float* out2 = h + (size_t)V * DD;

    void* yptr = nullptr;
    void* sptr = nullptr;
    cudaGetSymbolAddress(&yptr, g_Y);
    cudaGetSymbolAddress(&sptr, g_stats);
    cudaMemsetAsync(yptr, 0, (size_t)2 * V * DD * sizeof(float), 0);
    cudaMemsetAsync(sptr, 0, 2 * DD * sizeof(float), 0);

    edge_kernel<<<(E + 7) / 8, 256>>>(x, rel, enorm, src, dst, et, E, V, E / 2);
    gemm_kernel<<<(V + 63) / 64, 256>>>(x, loop_rel, in_w, out_w, loop_w, bias, h, V);
    bn_kernel<<<1024, 256>>>(h, V);
    relw_kernel<<<R, 128>>>(rel, w_rel, out2);
}

// round 4
// speedup vs baseline: 1.4797x; 1.4797x over previous
#include <cuda_runtime.h>
#include <cuda_bf16.h>
#include <cstdint>
#include <cstddef>

#define DD 128
#define VMAX 100000

// ---------------------------------------------------------------------------
// Global scratch (no allocs allowed)
// ---------------------------------------------------------------------------
__device__ float g_Y[2u * VMAX * DD];                    // Y_in | Y_out, fp32
__device__ float g_stats[2 * DD];                        // BN sum / sumsq
// W images: 12 chunks (in k0..3 | out k0..3 | loop k0..3), each [128 n][32 k] bf16
__device__ __align__(16) unsigned char g_Bhi[12 * 8192];
__device__ __align__(16) unsigned char g_Blo[12 * 8192];

// ---------------------------------------------------------------------------
// PTX helpers (generic-target safe: ldmatrix + mma.sync only)
// ---------------------------------------------------------------------------
__device__ __forceinline__ uint32_t smem_u32(const void* p) {
    uint32_t a;
    asm("{ .reg .u64 t; cvta.to.shared.u64 t, %1; cvt.u32.u64 %0, t; }" : "=r"(a) : "l"(p));
    return a;
}

#define LDSM4(r, addr)                                                          \
    asm volatile("ldmatrix.sync.aligned.m8n8.x4.shared.b16 {%0,%1,%2,%3}, [%4];" \
        : "=r"((r)[0]), "=r"((r)[1]), "=r"((r)[2]), "=r"((r)[3]) : "r"(addr))

#define MMA16816(d, a, b0, b1)                                                  \
    asm volatile("mma.sync.aligned.m16n8k16.row.col.f32.bf16.bf16.f32 "         \
        "{%0,%1,%2,%3}, {%4,%5,%6,%7}, {%8,%9}, {%0,%1,%2,%3};"                 \
        : "+f"((d)[0]), "+f"((d)[1]), "+f"((d)[2]), "+f"((d)[3])                \
        : "r"((a)[0]), "r"((a)[1]), "r"((a)[2]), "r"((a)[3]), "r"(b0), "r"(b1))

// ---------------------------------------------------------------------------
// Kernel 0: pre-split W into bf16 hi/lo chunk images, [n][k] rows of 32 bf16.
// chunk c: W = {in,out,loop}[c/4], k0 = (c%4)*32.  B[n][k] = W[(k0+k)*128+n]
// ---------------------------------------------------------------------------
__global__ void prep_w(const float* __restrict__ in_w, const float* __restrict__ out_w,
                       const float* __restrict__ loop_w) {
    int c = blockIdx.x;
    const float* W = (c < 4) ? in_w : (c < 8 ? out_w : loop_w);
    int k0 = (c & 3) * 32;
    __nv_bfloat16* bh = reinterpret_cast<__nv_bfloat16*>(g_Bhi + c * 8192);
    __nv_bfloat16* bl = reinterpret_cast<__nv_bfloat16*>(g_Blo + c * 8192);
    for (int i = threadIdx.x; i < 4096; i += blockDim.x) {
        int n = i >> 5, k = i & 31;
        float v = W[(size_t)(k0 + k) * DD + n];
        __nv_bfloat16 h = __float2bfloat16(v);
        __nv_bfloat16 l = __float2bfloat16(v - __bfloat162float(h));
        bh[n * 32 + k] = h;
        bl[n * 32 + k] = l;
    }
}

// ---------------------------------------------------------------------------
// Kernel 1: per-edge scatter.  Y_dir[dst] += norm * (x[src] * rel[et])
// ---------------------------------------------------------------------------
__global__ void edge_kernel(const float* __restrict__ x,
                            const float* __restrict__ rel,
                            const float* __restrict__ enorm,
                            const int* __restrict__ src,
                            const int* __restrict__ dst,
                            const int* __restrict__ et,
                            int E, int V, int half) {
    int warp = (blockIdx.x * blockDim.x + threadIdx.x) >> 5;
    if (warp >= E) return;
    int lane = threadIdx.x & 31;

    int   s = __ldg(&src[warp]);
    int   d = __ldg(&dst[warp]);
    int   t = __ldg(&et[warp]);
    float n = __ldg(&enorm[warp]);

    float4 xv = __ldg(reinterpret_cast<const float4*>(x)   + (size_t)s * 32 + lane);
    float4 rv = __ldg(reinterpret_cast<const float4*>(rel) + (size_t)t * 32 + lane);

    float a = n * xv.x * rv.x;
    float b = n * xv.y * rv.y;
    float c = n * xv.z * rv.z;
    float w = n * xv.w * rv.w;

    float* yp = g_Y + (size_t)((warp < half ? 0 : V) + d) * DD + lane * 4;
    asm volatile("red.global.add.v4.f32 [%0], {%1,%2,%3,%4};"
                 :: "l"(yp), "f"(a), "f"(b), "f"(c), "f"(w) : "memory");
}

// ---------------------------------------------------------------------------
// Kernel 2: mma.sync bf16 hi/lo GEMM.
//   h[v,:] = ( [Yin | Yout | x*loop_rel][v,:384] @ [in_w; out_w; loop_w] )/3 + bias
// CTA tile 128x128, 8 warps (warp tile 32x64), K chunks of 32.
// smem rows use 80B stride -> conflict-free ldmatrix.
// ---------------------------------------------------------------------------
#define ROWB 80   // bytes per smem row (32 bf16 data + pad)

__global__ void __launch_bounds__(256) gemm_mma(
    const float* __restrict__ x,
    const float* __restrict__ loop_rel,
    const float* __restrict__ bias,
    float* __restrict__ hout,
    int V) {

    __shared__ __align__(16) unsigned char sAh[128 * ROWB];
    __shared__ __align__(16) unsigned char sAl[128 * ROWB];
    __shared__ __align__(16) unsigned char sBh[128 * ROWB];
    __shared__ __align__(16) unsigned char sBl[128 * ROWB];

    const uint32_t uAh = smem_u32(sAh);
    const uint32_t uAl = smem_u32(sAl);
    const uint32_t uBh = smem_u32(sBh);
    const uint32_t uBl = smem_u32(sBl);

    const int tid  = threadIdx.x;
    const int wid  = tid >> 5;
    const int lane = tid & 31;
    const int wm   = wid & 3;    // 4 warps over M (32 rows each)
    const int wn   = wid >> 2;   // 2 warps over N (64 cols each)
    const int m0   = blockIdx.x * 128;

    float acc[2][8][4];
#pragma unroll
    for (int i = 0; i < 2; i++)
#pragma unroll
        for (int j = 0; j < 8; j++)
#pragma unroll
            for (int k = 0; k < 4; k++) acc[i][j][k] = 0.f;

    for (int c = 0; c < 12; c++) {
        __syncthreads();
        // ---- copy B chunk hi/lo: 128 rows x 8 uint2 each ----
        {
            const uint2* gh = reinterpret_cast<const uint2*>(g_Bhi + c * 8192);
            const uint2* gl = reinterpret_cast<const uint2*>(g_Blo + c * 8192);
#pragma unroll
            for (int j = 0; j < 4; j++) {
                int i = tid + j * 256;          // 0..1023
                int r = i >> 3, g = i & 7;
                *reinterpret_cast<uint2*>(sBh + r * ROWB + g * 8) = gh[i];
                *reinterpret_cast<uint2*>(sBl + r * ROWB + g * 8) = gl[i];
            }
        }
        // ---- load + split A chunk: 128 rows x 32 k fp32 ----
        {
            const int k0 = (c & 3) * 32;
            const float* Ab = (c < 4) ? g_Y : (c < 8 ? g_Y + (size_t)V * DD : x);
            const bool is_loop = (c >= 8);
#pragma unroll
            for (int j = 0; j < 4; j++) {
                int i = tid + j * 256;          // 0..1023 float4 slots
                int r = i >> 3, g = i & 7;
                int v = m0 + r;
                float4 z = make_float4(0.f, 0.f, 0.f, 0.f);
                if (v < V)
                    z = *reinterpret_cast<const float4*>(Ab + (size_t)v * DD + k0 + g * 4);
                if (is_loop) {
                    float4 lr = __ldg(reinterpret_cast<const float4*>(loop_rel + k0 + g * 4));
                    z.x *= lr.x; z.y *= lr.y; z.z *= lr.z; z.w *= lr.w;
                }
                __nv_bfloat16 hx = __float2bfloat16(z.x);
                __nv_bfloat16 hy = __float2bfloat16(z.y);
                __nv_bfloat16 hz = __float2bfloat16(z.z);
                __nv_bfloat16 hw = __float2bfloat16(z.w);
                __nv_bfloat16 lx = __float2bfloat16(z.x - __bfloat162float(hx));
                __nv_bfloat16 ly = __float2bfloat16(z.y - __bfloat162float(hy));
                __nv_bfloat16 lz = __float2bfloat16(z.z - __bfloat162float(hz));
                __nv_bfloat16 lw = __float2bfloat16(z.w - __bfloat162float(hw));
                __nv_bfloat162 h01(hx, hy), h23(hz, hw), l01(lx, ly), l23(lz, lw);
                uint2 hv = make_uint2(*reinterpret_cast<uint32_t*>(&h01),
                                      *reinterpret_cast<uint32_t*>(&h23));
                uint2 lv = make_uint2(*reinterpret_cast<uint32_t*>(&l01),
                                      *reinterpret_cast<uint32_t*>(&l23));
                *reinterpret_cast<uint2*>(sAh + r * ROWB + g * 8) = hv;
                *reinterpret_cast<uint2*>(sAl + r * ROWB + g * 8) = lv;
            }
        }
        __syncthreads();

        // ---- mma over 2 K16 steps ----
#pragma unroll
        for (int k16 = 0; k16 < 2; k16++) {
            const uint32_t kb = k16 * 32 + ((lane >> 4) << 4);
            const uint32_t arow = (uint32_t)(wm * 32 + (lane & 15)) * ROWB + kb;
            const uint32_t brow = (uint32_t)(wn * 64 + (lane & 15)) * ROWB + kb;

            uint32_t ah[2][4], al[2][4], bh[4][4], bl[4][4];
#pragma unroll
            for (int mt = 0; mt < 2; mt++) LDSM4(ah[mt], uAh + arow + mt * 16 * ROWB);
#pragma unroll
            for (int nb = 0; nb < 4; nb++) LDSM4(bh[nb], uBh + brow + nb * 16 * ROWB);
            // hi * hi
#pragma unroll
            for (int mt = 0; mt < 2; mt++)
#pragma unroll
                for (int nb = 0; nb < 4; nb++) {
                    MMA16816(acc[mt][nb * 2 + 0], ah[mt], bh[nb][0], bh[nb][2]);
                    MMA16816(acc[mt][nb * 2 + 1], ah[mt], bh[nb][1], bh[nb][3]);
                }
            // hi * lo
#pragma unroll
            for (int nb = 0; nb < 4; nb++) LDSM4(bl[nb], uBl + brow + nb * 16 * ROWB);
#pragma unroll
            for (int mt = 0; mt < 2; mt++)
#pragma unroll
                for (int nb = 0; nb < 4; nb++) {
                    MMA16816(acc[mt][nb * 2 + 0], ah[mt], bl[nb][0], bl[nb][2]);
                    MMA16816(acc[mt][nb * 2 + 1], ah[mt], bl[nb][1], bl[nb][3]);
                }
            // lo * hi
#pragma unroll
            for (int mt = 0; mt < 2; mt++) LDSM4(al[mt], uAl + arow + mt * 16 * ROWB);
#pragma unroll
            for (int mt = 0; mt < 2; mt++)
#pragma unroll
                for (int nb = 0; nb < 4; nb++) {
                    MMA16816(acc[mt][nb * 2 + 0], al[mt], bh[nb][0], bh[nb][2]);
                    MMA16816(acc[mt][nb * 2 + 1], al[mt], bh[nb][1], bh[nb][3]);
                }
        }
    }

    // ---- epilogue: /3 + bias, store ----
    const float third = 1.f / 3.f;
#pragma unroll
    for (int mt = 0; mt < 2; mt++) {
        int rowa = m0 + wm * 32 + mt * 16 + (lane >> 2);
        int rowb = rowa + 8;
#pragma unroll
        for (int nt = 0; nt < 8; nt++) {
            int col = wn * 64 + nt * 8 + (lane & 3) * 2;
            float2 bv = *reinterpret_cast<const float2*>(bias + col);
            if (rowa < V) {
                float2 o;
                o.x = acc[mt][nt][0] * third + bv.x;
                o.y = acc[mt][nt][1] * third + bv.y;
                *reinterpret_cast<float2*>(hout + (size_t)rowa * DD + col) = o;
            }
            if (rowb < V) {
                float2 o;
                o.x = acc[mt][nt][2] * third + bv.x;
                o.y = acc[mt][nt][3] * third + bv.y;
                *reinterpret_cast<float2*>(hout + (size_t)rowb * DD + col) = o;
            }
        }
    }
}

// ---------------------------------------------------------------------------
// Kernel 3: BN column stats over h
// ---------------------------------------------------------------------------
__global__ void stats_kernel(const float* __restrict__ h, int V) {
    __shared__ float ss[128], sq[128];
    int tid = threadIdx.x;
    if (tid < 128) { ss[tid] = 0.f; sq[tid] = 0.f; }
    __syncthreads();
    int c  = (tid & 31) * 4;
    int rw = tid >> 5;
    float cs[4] = {0.f, 0.f, 0.f, 0.f};
    float cq[4] = {0.f, 0.f, 0.f, 0.f};
    for (int v = blockIdx.x * 8 + rw; v < V; v += gridDim.x * 8) {
        float4 hv = *reinterpret_cast<const float4*>(h + (size_t)v * DD + c);
        cs[0] += hv.x; cq[0] += hv.x * hv.x;
        cs[1] += hv.y; cq[1] += hv.y * hv.y;
        cs[2] += hv.z; cq[2] += hv.z * hv.z;
        cs[3] += hv.w; cq[3] += hv.w * hv.w;
    }
#pragma unroll
    for (int j = 0; j < 4; j++) {
        atomicAdd(&ss[c + j], cs[j]);
        atomicAdd(&sq[c + j], cq[j]);
    }
    __syncthreads();
    if (tid < 128) {
        atomicAdd(&g_stats[tid],       ss[tid]);
        atomicAdd(&g_stats[128 + tid], sq[tid]);
    }
}

// ---------------------------------------------------------------------------
// Kernel 4: BatchNorm + ReLU, in place on h
// ---------------------------------------------------------------------------
__global__ void bn_kernel(float* __restrict__ h, int V) {
    __shared__ float ms[128];
    __shared__ float rs[128];
    if (threadIdx.x < 128) {
        float invn = 1.f / (float)V;
        float s  = g_stats[threadIdx.x];
        float sq = g_stats[128 + threadIdx.x];
        float m  = s * invn;
        float var = sq * invn - m * m;
        ms[threadIdx.x] = m;
        rs[threadIdx.x] = rsqrtf(var + 1e-5f);
    }
    __syncthreads();
    size_t total = (size_t)V * 32;
    float4* h4 = reinterpret_cast<float4*>(h);
    for (size_t i = (size_t)blockIdx.x * blockDim.x + threadIdx.x; i < total;
         i += (size_t)gridDim.x * blockDim.x) {
        int c4 = (int)(i & 31) * 4;
        float4 hv = h4[i];
        hv.x = fmaxf((hv.x - ms[c4 + 0]) * rs[c4 + 0], 0.f);
        hv.y = fmaxf((hv.y - ms[c4 + 1]) * rs[c4 + 1], 0.f);
        hv.z = fmaxf((hv.z - ms[c4 + 2]) * rs[c4 + 2], 0.f);
        hv.w = fmaxf((hv.w - ms[c4 + 3]) * rs[c4 + 3], 0.f);
        h4[i] = hv;
    }
}

// ---------------------------------------------------------------------------
// Kernel 5: rel_repr @ w_rel, 4 rel rows per block
// ---------------------------------------------------------------------------
__global__ void relw_kernel(const float* __restrict__ rel,
                            const float* __restrict__ w_rel,
                            float* __restrict__ out, int R) {
    __shared__ float rr[4][128];
    int r0 = blockIdx.x * 4;
    int c = threadIdx.x;
#pragma unroll
    for (int j = 0; j < 4; j++)
        rr[j][c] = (r0 + j < R) ? rel[(size_t)(r0 + j) * DD + c] : 0.f;
    __syncthreads();
    float a0 = 0.f, a1 = 0.f, a2 = 0.f, a3 = 0.f;
#pragma unroll 4
    for (int k = 0; k < 128; k++) {
        float w = __ldg(&w_rel[(size_t)k * DD + c]);
        a0 += rr[0][k] * w;
        a1 += rr[1][k] * w;
        a2 += rr[2][k] * w;
        a3 += rr[3][k] * w;
    }
    if (r0 + 0 < R) out[(size_t)(r0 + 0) * DD + c] = a0;
    if (r0 + 1 < R) out[(size_t)(r0 + 1) * DD + c] = a1;
    if (r0 + 2 < R) out[(size_t)(r0 + 2) * DD + c] = a2;
    if (r0 + 3 < R) out[(size_t)(r0 + 3) * DD + c] = a3;
}

// ---------------------------------------------------------------------------
extern "C" void kernel_launch(void* const* d_in, const int* in_sizes, int n_in,
                              void* d_out, int out_size) {
    const float* x        = (const float*)d_in[0];
    const float* rel      = (const float*)d_in[1];
    const float* enorm    = (const float*)d_in[2];
    const float* in_w     = (const float*)d_in[3];
    const float* out_w    = (const float*)d_in[4];
    const float* loop_w   = (const float*)d_in[5];
    const float* w_rel    = (const float*)d_in[6];
    const float* loop_rel = (const float*)d_in[7];
    const float* bias     = (const float*)d_in[8];
    const int*   src      = (const int*)d_in[9];
    const int*   dst      = (const int*)d_in[10];
    const int*   et       = (const int*)d_in[11];

    int V = in_sizes[0] / DD;
    int R = in_sizes[1] / DD;
    int E = in_sizes[2];

    float* h    = (float*)d_out;
    float* out2 = h + (size_t)V * DD;

    void* yptr = nullptr; void* sptr = nullptr;
    cudaGetSymbolAddress(&yptr, g_Y);
    cudaGetSymbolAddress(&sptr, g_stats);
    cudaMemsetAsync(yptr, 0, (size_t)2 * V * DD * sizeof(float), 0);
    cudaMemsetAsync(sptr, 0, 2 * DD * sizeof(float), 0);

    prep_w<<<12, 256>>>(in_w, out_w, loop_w);
    edge_kernel<<<(E + 7) / 8, 256>>>(x, rel, enorm, src, dst, et, E, V, E / 2);
    gemm_mma<<<(V + 127) / 128, 256>>>(x, loop_rel, bias, h, V);
    stats_kernel<<<512, 256>>>(h, V);
    bn_kernel<<<1024, 256>>>(h, V);
    relw_kernel<<<(R + 3) / 4, 128>>>(rel, w_rel, out2, R);
}

// round 6
// speedup vs baseline: 1.5132x; 1.0226x over previous
#include <cuda_runtime.h>
#include <cuda_bf16.h>
#include <cstdint>
#include <cstddef>

#define DD 128
#define VMAX 100000

// ---------------------------------------------------------------------------
// Global scratch (no allocs allowed)
// ---------------------------------------------------------------------------
__device__ float g_Y[2u * VMAX * DD];                    // Y_in | Y_out, fp32
__device__ float g_stats[2 * DD];                        // BN sum / sumsq
// W images: 12 chunks (in k0..3 | out k0..3 | loop k0..3), each [128 n][32 k] bf16
__device__ __align__(16) unsigned char g_Bhi[12 * 8192];
__device__ __align__(16) unsigned char g_Blo[12 * 8192];

// ---------------------------------------------------------------------------
// PTX helpers (generic-target safe: ldmatrix + mma.sync only)
// ---------------------------------------------------------------------------
__device__ __forceinline__ uint32_t smem_u32(const void* p) {
    uint32_t a;
    asm("{ .reg .u64 t; cvta.to.shared.u64 t, %1; cvt.u32.u64 %0, t; }" : "=r"(a) : "l"(p));
    return a;
}

#define LDSM4(r, addr)                                                          \
    asm volatile("ldmatrix.sync.aligned.m8n8.x4.shared.b16 {%0,%1,%2,%3}, [%4];" \
        : "=r"((r)[0]), "=r"((r)[1]), "=r"((r)[2]), "=r"((r)[3]) : "r"(addr))

#define MMA16816(d, a, b0, b1)                                                  \
    asm volatile("mma.sync.aligned.m16n8k16.row.col.f32.bf16.bf16.f32 "         \
        "{%0,%1,%2,%3}, {%4,%5,%6,%7}, {%8,%9}, {%0,%1,%2,%3};"                 \
        : "+f"((d)[0]), "+f"((d)[1]), "+f"((d)[2]), "+f"((d)[3])                \
        : "r"((a)[0]), "r"((a)[1]), "r"((a)[2]), "r"((a)[3]), "r"(b0), "r"(b1))

// ---------------------------------------------------------------------------
// Kernel 0: pre-split W into bf16 hi/lo chunk images, [n][k] rows of 32 bf16.
// ---------------------------------------------------------------------------
__global__ void prep_w(const float* __restrict__ in_w, const float* __restrict__ out_w,
                       const float* __restrict__ loop_w) {
    int c = blockIdx.x;
    const float* W = (c < 4) ? in_w : (c < 8 ? out_w : loop_w);
    int k0 = (c & 3) * 32;
    __nv_bfloat16* bh = reinterpret_cast<__nv_bfloat16*>(g_Bhi + c * 8192);
    __nv_bfloat16* bl = reinterpret_cast<__nv_bfloat16*>(g_Blo + c * 8192);
    for (int i = threadIdx.x; i < 4096; i += blockDim.x) {
        int n = i >> 5, k = i & 31;
        float v = W[(size_t)(k0 + k) * DD + n];
        __nv_bfloat16 h = __float2bfloat16(v);
        __nv_bfloat16 l = __float2bfloat16(v - __bfloat162float(h));
        bh[n * 32 + k] = h;
        bl[n * 32 + k] = l;
    }
}

// ---------------------------------------------------------------------------
// Kernel 1: per-edge scatter for ONE direction.  yb[dst] += norm*(x[src]*rel[et])
// ---------------------------------------------------------------------------
__global__ void edge_kernel(const float* __restrict__ x,
                            const float* __restrict__ rel,
                            const float* __restrict__ enorm,
                            const int* __restrict__ src,
                            const int* __restrict__ dst,
                            const int* __restrict__ et,
                            int n_edges,
                            float* __restrict__ yb) {
    int e = (blockIdx.x * blockDim.x + threadIdx.x) >> 5;
    if (e >= n_edges) return;
    int lane = threadIdx.x & 31;

    int   s = __ldg(&src[e]);
    int   d = __ldg(&dst[e]);
    int   t = __ldg(&et[e]);
    float n = __ldg(&enorm[e]);

    float4 xv = __ldg(reinterpret_cast<const float4*>(x)   + (size_t)s * 32 + lane);
    float4 rv = __ldg(reinterpret_cast<const float4*>(rel) + (size_t)t * 32 + lane);

    float a = n * xv.x * rv.x;
    float b = n * xv.y * rv.y;
    float c = n * xv.z * rv.z;
    float w = n * xv.w * rv.w;

    float* yp = yb + (size_t)d * DD + lane * 4;
    asm volatile("red.global.add.v4.f32 [%0], {%1,%2,%3,%4};"
                 :: "l"(yp), "f"(a), "f"(b), "f"(c), "f"(w) : "memory");
}

// ---------------------------------------------------------------------------
// Kernel 2: mma.sync bf16 hi/lo GEMM with fused BN-stats accumulation.
// ---------------------------------------------------------------------------
#define ROWB 80   // bytes per smem row (32 bf16 data + pad)

__global__ void __launch_bounds__(256, 2) gemm_mma(
    const float* __restrict__ x,
    const float* __restrict__ loop_rel,
    const float* __restrict__ bias,
    float* __restrict__ hout,
    int V) {

    __shared__ __align__(16) unsigned char sAh[128 * ROWB];
    __shared__ __align__(16) unsigned char sAl[128 * ROWB];
    __shared__ __align__(16) unsigned char sBh[128 * ROWB];
    __shared__ __align__(16) unsigned char sBl[128 * ROWB];

    const uint32_t uAh = smem_u32(sAh);
    const uint32_t uAl = smem_u32(sAl);
    const uint32_t uBh = smem_u32(sBh);
    const uint32_t uBl = smem_u32(sBl);

    const int tid  = threadIdx.x;
    const int wid  = tid >> 5;
    const int lane = tid & 31;
    const int wm   = wid & 3;    // 4 warps over M (32 rows each)
    const int wn   = wid >> 2;   // 2 warps over N (64 cols each)
    const int m0   = blockIdx.x * 128;

    float acc[2][8][4];
#pragma unroll
    for (int i = 0; i < 2; i++)
#pragma unroll
        for (int j = 0; j < 8; j++)
#pragma unroll
            for (int k = 0; k < 4; k++) acc[i][j][k] = 0.f;

    for (int c = 0; c < 12; c++) {
        __syncthreads();
        // ---- copy B chunk hi/lo ----
        {
            const uint2* gh = reinterpret_cast<const uint2*>(g_Bhi + c * 8192);
            const uint2* gl = reinterpret_cast<const uint2*>(g_Blo + c * 8192);
#pragma unroll
            for (int j = 0; j < 4; j++) {
                int i = tid + j * 256;
                int r = i >> 3, g = i & 7;
                *reinterpret_cast<uint2*>(sBh + r * ROWB + g * 8) = gh[i];
                *reinterpret_cast<uint2*>(sBl + r * ROWB + g * 8) = gl[i];
            }
        }
        // ---- load + split A chunk ----
        {
            const int k0 = (c & 3) * 32;
            const float* Ab = (c < 4) ? g_Y : (c < 8 ? g_Y + (size_t)V * DD : x);
            const bool is_loop = (c >= 8);
#pragma unroll
            for (int j = 0; j < 4; j++) {
                int i = tid + j * 256;
                int r = i >> 3, g = i & 7;
                int v = m0 + r;
                float4 z = make_float4(0.f, 0.f, 0.f, 0.f);
                if (v < V)
                    z = *reinterpret_cast<const float4*>(Ab + (size_t)v * DD + k0 + g * 4);
                if (is_loop) {
                    float4 lr = __ldg(reinterpret_cast<const float4*>(loop_rel + k0 + g * 4));
                    z.x *= lr.x; z.y *= lr.y; z.z *= lr.z; z.w *= lr.w;
                }
                __nv_bfloat16 hx = __float2bfloat16(z.x);
                __nv_bfloat16 hy = __float2bfloat16(z.y);
                __nv_bfloat16 hz = __float2bfloat16(z.z);
                __nv_bfloat16 hw = __float2bfloat16(z.w);
                __nv_bfloat16 lx = __float2bfloat16(z.x - __bfloat162float(hx));
                __nv_bfloat16 ly = __float2bfloat16(z.y - __bfloat162float(hy));
                __nv_bfloat16 lz = __float2bfloat16(z.z - __bfloat162float(hz));
                __nv_bfloat16 lw = __float2bfloat16(z.w - __bfloat162float(hw));
                __nv_bfloat162 h01(hx, hy), h23(hz, hw), l01(lx, ly), l23(lz, lw);
                uint2 hv = make_uint2(*reinterpret_cast<uint32_t*>(&h01),
                                      *reinterpret_cast<uint32_t*>(&h23));
                uint2 lv = make_uint2(*reinterpret_cast<uint32_t*>(&l01),
                                      *reinterpret_cast<uint32_t*>(&l23));
                *reinterpret_cast<uint2*>(sAh + r * ROWB + g * 8) = hv;
                *reinterpret_cast<uint2*>(sAl + r * ROWB + g * 8) = lv;
            }
        }
        __syncthreads();

        // ---- mma over 2 K16 steps ----
#pragma unroll
        for (int k16 = 0; k16 < 2; k16++) {
            const uint32_t kb = k16 * 32 + ((lane >> 4) << 4);
            const uint32_t arow = (uint32_t)(wm * 32 + (lane & 15)) * ROWB + kb;
            const uint32_t brow = (uint32_t)(wn * 64 + (lane & 15)) * ROWB + kb;

            uint32_t ah[2][4], al[2][4], bh[4][4], bl[4][4];
#pragma unroll
            for (int mt = 0; mt < 2; mt++) LDSM4(ah[mt], uAh + arow + mt * 16 * ROWB);
#pragma unroll
            for (int nb = 0; nb < 4; nb++) LDSM4(bh[nb], uBh + brow + nb * 16 * ROWB);
#pragma unroll
            for (int mt = 0; mt < 2; mt++)
#pragma unroll
                for (int nb = 0; nb < 4; nb++) {
                    MMA16816(acc[mt][nb * 2 + 0], ah[mt], bh[nb][0], bh[nb][2]);
                    MMA16816(acc[mt][nb * 2 + 1], ah[mt], bh[nb][1], bh[nb][3]);
                }
#pragma unroll
            for (int nb = 0; nb < 4; nb++) LDSM4(bl[nb], uBl + brow + nb * 16 * ROWB);
#pragma unroll
            for (int mt = 0; mt < 2; mt++)
#pragma unroll
                for (int nb = 0; nb < 4; nb++) {
                    MMA16816(acc[mt][nb * 2 + 0], ah[mt], bl[nb][0], bl[nb][2]);
                    MMA16816(acc[mt][nb * 2 + 1], ah[mt], bl[nb][1], bl[nb][3]);
                }
#pragma unroll
            for (int mt = 0; mt < 2; mt++) LDSM4(al[mt], uAl + arow + mt * 16 * ROWB);
#pragma unroll
            for (int mt = 0; mt < 2; mt++)
#pragma unroll
                for (int nb = 0; nb < 4; nb++) {
                    MMA16816(acc[mt][nb * 2 + 0], al[mt], bh[nb][0], bh[nb][2]);
                    MMA16816(acc[mt][nb * 2 + 1], al[mt], bh[nb][1], bh[nb][3]);
                }
        }
    }

    // ---- epilogue: /3 + bias, store h, accumulate BN stats ----
    const float third = 1.f / 3.f;
    float ssum[16], ssq[16];
#pragma unroll
    for (int i = 0; i < 16; i++) { ssum[i] = 0.f; ssq[i] = 0.f; }

#pragma unroll
    for (int mt = 0; mt < 2; mt++) {
        int rowa = m0 + wm * 32 + mt * 16 + (lane >> 2);
        int rowb = rowa + 8;
#pragma unroll
        for (int nt = 0; nt < 8; nt++) {
            int col = wn * 64 + nt * 8 + (lane & 3) * 2;
            float2 bv = *reinterpret_cast<const float2*>(bias + col);
            float h0 = acc[mt][nt][0] * third + bv.x;
            float h1 = acc[mt][nt][1] * third + bv.y;
            float h2 = acc[mt][nt][2] * third + bv.x;
            float h3 = acc[mt][nt][3] * third + bv.y;
            if (rowa < V) {
                *reinterpret_cast<float2*>(hout + (size_t)rowa * DD + col) =
                    make_float2(h0, h1);
                ssum[nt * 2 + 0] += h0; ssq[nt * 2 + 0] += h0 * h0;
                ssum[nt * 2 + 1] += h1; ssq[nt * 2 + 1] += h1 * h1;
            }
            if (rowb < V) {
                *reinterpret_cast<float2*>(hout + (size_t)rowb * DD + col) =
                    make_float2(h2, h3);
                ssum[nt * 2 + 0] += h2; ssq[nt * 2 + 0] += h2 * h2;
                ssum[nt * 2 + 1] += h3; ssq[nt * 2 + 1] += h3 * h3;
            }
        }
    }
    // reduce over lane bits 2..4 (rows within warp)
#pragma unroll
    for (int i = 0; i < 16; i++) {
#pragma unroll
        for (int off = 4; off <= 16; off <<= 1) {
            ssum[i] += __shfl_xor_sync(0xFFFFFFFFu, ssum[i], off);
            ssq[i]  += __shfl_xor_sync(0xFFFFFFFFu, ssq[i],  off);
        }
    }
    __syncthreads();  // smem reuse
    float* Ssum = reinterpret_cast<float*>(sAh);   // [8][128]
    float* Ssq  = reinterpret_cast<float*>(sAl);   // [8][128]
#pragma unroll
    for (int j = 0; j < 4; j++) { Ssum[tid + j * 256] = 0.f; Ssq[tid + j * 256] = 0.f; }
    __syncthreads();
    if (lane < 4) {
#pragma unroll
        for (int nt = 0; nt < 8; nt++) {
            int col = wn * 64 + nt * 8 + lane * 2;
            Ssum[wid * 128 + col]     = ssum[nt * 2 + 0];
            Ssum[wid * 128 + col + 1] = ssum[nt * 2 + 1];
            Ssq [wid * 128 + col]     = ssq[nt * 2 + 0];
            Ssq [wid * 128 + col + 1] = ssq[nt * 2 + 1];
        }
    }
    __syncthreads();
    if (tid < 128) {
        float a = 0.f, b = 0.f;
#pragma unroll
        for (int w = 0; w < 8; w++) { a += Ssum[w * 128 + tid]; b += Ssq[w * 128 + tid]; }
        atomicAdd(&g_stats[tid],       a);
        atomicAdd(&g_stats[128 + tid], b);
    }
}

// ---------------------------------------------------------------------------
// Kernel 3: BatchNorm + ReLU, in place on h
// ---------------------------------------------------------------------------
__global__ void bn_kernel(float* __restrict__ h, int V) {
    __shared__ float ms[128];
    __shared__ float rs[128];
    if (threadIdx.x < 128) {
        float invn = 1.f / (float)V;
        float s  = g_stats[threadIdx.x];
        float sq = g_stats[128 + threadIdx.x];
        float m  = s * invn;
        float var = sq * invn - m * m;
        ms[threadIdx.x] = m;
        rs[threadIdx.x] = rsqrtf(var + 1e-5f);
    }
    __syncthreads();
    size_t total = (size_t)V * 32;
    float4* h4 = reinterpret_cast<float4*>(h);
    for (size_t i = (size_t)blockIdx.x * blockDim.x + threadIdx.x; i < total;
         i += (size_t)gridDim.x * blockDim.x) {
        int c4 = (int)(i & 31) * 4;
        float4 hv = h4[i];
        hv.x = fmaxf((hv.x - ms[c4 + 0]) * rs[c4 + 0], 0.f);
        hv.y = fmaxf((hv.y - ms[c4 + 1]) * rs[c4 + 1], 0.f);
        hv.z = fmaxf((hv.z - ms[c4 + 2]) * rs[c4 + 2], 0.f);
        hv.w = fmaxf((hv.w - ms[c4 + 3]) * rs[c4 + 3], 0.f);
        h4[i] = hv;
    }
}

// ---------------------------------------------------------------------------
// Kernel 4: rel_repr @ w_rel, 4 rel rows per block
// ---------------------------------------------------------------------------
__global__ void relw_kernel(const float* __restrict__ rel,
                            const float* __restrict__ w_rel,
                            float* __restrict__ out, int R) {
    __shared__ float rr[4][128];
    int r0 = blockIdx.x * 4;
    int c = threadIdx.x;
#pragma unroll
    for (int j = 0; j < 4; j++)
        rr[j][c] = (r0 + j < R) ? rel[(size_t)(r0 + j) * DD + c] : 0.f;
    __syncthreads();
    float a0 = 0.f, a1 = 0.f, a2 = 0.f, a3 = 0.f;
#pragma unroll 4
    for (int k = 0; k < 128; k++) {
        float w = __ldg(&w_rel[(size_t)k * DD + c]);
        a0 += rr[0][k] * w;
        a1 += rr[1][k] * w;
        a2 += rr[2][k] * w;
        a3 += rr[3][k] * w;
    }
    if (r0 + 0 < R) out[(size_t)(r0 + 0) * DD + c] = a0;
    if (r0 + 1 < R) out[(size_t)(r0 + 1) * DD + c] = a1;
    if (r0 + 2 < R) out[(size_t)(r0 + 2) * DD + c] = a2;
    if (r0 + 3 < R) out[(size_t)(r0 + 3) * DD + c] = a3;
}

// ---------------------------------------------------------------------------
extern "C" void kernel_launch(void* const* d_in, const int* in_sizes, int n_in,
                              void* d_out, int out_size) {
    const float* x        = (const float*)d_in[0];
    const float* rel      = (const float*)d_in[1];
    const float* enorm    = (const float*)d_in[2];
    const float* in_w     = (const float*)d_in[3];
    const float* out_w    = (const float*)d_in[4];
    const float* loop_w   = (const float*)d_in[5];
    const float* w_rel    = (const float*)d_in[6];
    const float* loop_rel = (const float*)d_in[7];
    const float* bias     = (const float*)d_in[8];
    const int*   src      = (const int*)d_in[9];
    const int*   dst      = (const int*)d_in[10];
    const int*   et       = (const int*)d_in[11];

    int V = in_sizes[0] / DD;
    int R = in_sizes[1] / DD;
    int E = in_sizes[2];
    int half = E / 2;

    float* h    = (float*)d_out;
    float* out2 = h + (size_t)V * DD;

    void* yptr = nullptr; void* sptr = nullptr;
    cudaGetSymbolAddress(&yptr, g_Y);
    cudaGetSymbolAddress(&sptr, g_stats);
    float* Yin  = (float*)yptr;
    float* Yout = Yin + (size_t)V * DD;
    cudaMemsetAsync(yptr, 0, (size_t)2 * V * DD * sizeof(float), 0);
    cudaMemsetAsync(sptr, 0, 2 * DD * sizeof(float), 0);

    prep_w<<<12, 256>>>(in_w, out_w, loop_w);
    // two passes: per-launch working set (x + half of Y) fits in L2
    edge_kernel<<<(half + 7) / 8, 256>>>(x, rel, enorm, src, dst, et, half, Yin);
    edge_kernel<<<(E - half + 7) / 8, 256>>>(x, rel, enorm + half, src + half,
                                             dst + half, et + half, E - half, Yout);
    gemm_mma<<<(V + 127) / 128, 256>>>(x, loop_rel, bias, h, V);
    bn_kernel<<<1024, 256>>>(h, V);
    relw_kernel<<<(R + 3) / 4, 128>>>(rel, w_rel, out2, R);
}